// round 14
// baseline (speedup 1.0000x reference)
#include <cuda_runtime.h>
#include <cuda_fp16.h>
#include <math.h>
#include <cstdint>

// ---------------- problem constants ----------------
#define BB    32
#define HH    56
#define WWI   56
#define LTOK  3136          // 56*56
#define CDIM  512
#define NH    16
#define HDIM  32
#define WSZ   8
#define NTOK  64            // 8*8
#define SHFT  4
#define NWH   7
#define NWIN  49            // 7*7
#define NWTOT 1568          // BB*NWIN
#define MROWS 100352        // BB*LTOK = NWTOT*NTOK
#define HID   2048
#define QKVC  1536

// weight offsets in g_wh (halves)
#define WQ_OFF  0
#define WP_OFF  786432            // 1536*512
#define W1_OFF  1048576           // + 512*512
#define W2_OFF  2097152           // + 2048*512
#define WTOT    3145728           // + 512*2048

// ---------------- static device scratch ----------------
__device__ __half g_xw[(size_t)MROWS * CDIM];      // LN outputs (fp16)
__device__ __half g_qkv[(size_t)MROWS * QKVC];     // qkv fp16; q-region reused as attn out
__device__ float  g_x1[(size_t)MROWS * CDIM];      // residual after attention (fp32)
__device__ __half g_hidden[(size_t)MROWS * HID];   // MLP hidden fp16
__device__ __half g_wh[WTOT];                      // fp16 weights
__device__ float  g_pbm[4 * NH * 4096];            // pos-bias + mask, fragment layout

// ---------------- helpers ----------------
__device__ __forceinline__ uint32_t smem_u32(const void* p) {
    uint32_t a;
    asm("{ .reg .u64 t; cvta.to.shared.u64 t, %1; cvt.u32.u64 %0, t; }" : "=r"(a) : "l"(p));
    return a;
}
#define CP_ASYNC16(dst, src) \
    asm volatile("cp.async.cg.shared.global [%0], [%1], 16;" :: "r"(dst), "l"(src))
#define CP_COMMIT() asm volatile("cp.async.commit_group;" ::: "memory")
#define CP_WAIT(n)  asm volatile("cp.async.wait_group %0;" :: "n"(n) : "memory")

#define LDSM4(r, addr) \
    asm volatile("ldmatrix.sync.aligned.m8n8.x4.shared.b16 {%0,%1,%2,%3}, [%4];" \
        : "=r"((r)[0]), "=r"((r)[1]), "=r"((r)[2]), "=r"((r)[3]) : "r"(addr))
#define LDSM4T(r, addr) \
    asm volatile("ldmatrix.sync.aligned.m8n8.x4.trans.shared.b16 {%0,%1,%2,%3}, [%4];" \
        : "=r"((r)[0]), "=r"((r)[1]), "=r"((r)[2]), "=r"((r)[3]) : "r"(addr))

__device__ __forceinline__ void mma_f16(float* d, const uint32_t* a, uint32_t b0, uint32_t b1) {
    asm volatile(
        "mma.sync.aligned.m16n8k16.row.col.f32.f16.f16.f32 "
        "{%0,%1,%2,%3}, {%4,%5,%6,%7}, {%8,%9}, {%0,%1,%2,%3};"
        : "+f"(d[0]), "+f"(d[1]), "+f"(d[2]), "+f"(d[3])
        : "r"(a[0]), "r"(a[1]), "r"(a[2]), "r"(a[3]), "r"(b0), "r"(b1));
}

// windowed row p -> flat row in original (B, H*W) layout
__device__ __forceinline__ size_t win_row_to_flat(int p) {
    int b   = p / LTOK;
    int rem = p - b * LTOK;
    int wl  = rem >> 6;
    int t   = rem & 63;
    int wh  = wl / NWH;
    int ww  = wl - wh * NWH;
    int r   = (wh * WSZ + (t >> 3) + SHFT) % HH;
    int c   = (ww * WSZ + (t & 7)  + SHFT) % WWI;
    return (size_t)b * LTOK + (size_t)r * WWI + c;
}

// ---------------- weight fp32 -> fp16 conversion ----------------
__global__ __launch_bounds__(256)
void cvtw_kernel(const float* __restrict__ wq, const float* __restrict__ wp,
                 const float* __restrict__ w1, const float* __restrict__ w2) {
    int i4 = (blockIdx.x * 256 + threadIdx.x) * 4;
    const float* src;
    int off;
    if      (i4 < WP_OFF) { src = wq; off = i4; }
    else if (i4 < W1_OFF) { src = wp; off = i4 - WP_OFF; }
    else if (i4 < W2_OFF) { src = w1; off = i4 - W1_OFF; }
    else                  { src = w2; off = i4 - W2_OFF; }
    float4 v = *(const float4*)(src + off);
    __half2 a = __floats2half2_rn(v.x, v.y);
    __half2 b = __floats2half2_rn(v.z, v.w);
    uint2 u;
    u.x = *(uint32_t*)&a;
    u.y = *(uint32_t*)&b;
    *(uint2*)&g_wh[i4] = u;
}

// ---------------- pos-bias + mask table, fragment layout ----------------
__global__ __launch_bounds__(256)
void posbias_kernel(const float* __restrict__ w1, const float* __restrict__ b1,
                    const float* __restrict__ w2, const float* __restrict__ b2) {
    int blk = blockIdx.x;            // cls*16 + h
    int cls = blk >> 4, h = blk & 15;
    int rh = cls >> 1, rw = cls & 1;
    for (int f = threadIdx.x; f < 1024; f += 256) {
        int lane = f & 31, f4 = (f >> 5) & 3, qc = f >> 7;
        int mt = qc >> 1, hf = qc & 1, g = lane >> 2, tig = lane & 3;
        int n = mt * 16 + g + 8 * hf;           // query token
        float out[4];
#pragma unroll
        for (int e = 0; e < 4; ++e) {
            int nt = f4 * 2 + (e >> 1), j = e & 1;
            int m = nt * 8 + tig * 2 + j;       // key token
            float dh = (float)((n >> 3) - (m >> 3));
            float dw = (float)((n & 7) - (m & 7));
            float fh = (dh > 0.f) ? log1pf(dh) : ((dh < 0.f) ? -log1pf(-dh) : 0.f);
            float fw = (dw > 0.f) ? log1pf(dw) : ((dw < 0.f) ? -log1pf(-dw) : 0.f);
            float acc = b2[h];
#pragma unroll
            for (int o = 0; o < 32; ++o) {
                float hv = fmaxf(w1[2 * o] * fh + w1[2 * o + 1] * fw + b1[o], 0.f);
                acc += w2[h * 32 + o] * hv;
            }
            int gin = rh ? (((n >> 3) < 4) ? 1 : 2) : 0;
            int gjn = rw ? (((n & 7) < 4) ? 1 : 2) : 0;
            int gim = rh ? (((m >> 3) < 4) ? 1 : 2) : 0;
            int gjm = rw ? (((m & 7) < 4) ? 1 : 2) : 0;
            if (gin != gim || gjn != gjm) acc -= 100.f;
            out[e] = acc;
        }
        *(float4*)&g_pbm[(size_t)blk * 4096 + f * 4] = make_float4(out[0], out[1], out[2], out[3]);
    }
}

// ---------------- LayerNorm: warp-per-row, fp32 in, fp16 out ----------------
__global__ __launch_bounds__(256)
void ln_kernel(const float* __restrict__ in, const float* __restrict__ gamma,
               const float* __restrict__ beta, __half* __restrict__ out, int gather) {
    int warp = threadIdx.x >> 5, lane = threadIdx.x & 31;
    int p = blockIdx.x * 8 + warp;
    size_t srow = gather ? win_row_to_flat(p) : (size_t)p;
    const float4* src = (const float4*)(in + srow * CDIM);
    float4 v[4];
#pragma unroll
    for (int i = 0; i < 4; ++i) v[i] = src[lane + 32 * i];
    float s = 0.f, q = 0.f;
#pragma unroll
    for (int i = 0; i < 4; ++i) {
        s += v[i].x + v[i].y + v[i].z + v[i].w;
        q += v[i].x * v[i].x + v[i].y * v[i].y + v[i].z * v[i].z + v[i].w * v[i].w;
    }
#pragma unroll
    for (int off = 16; off > 0; off >>= 1) {
        s += __shfl_xor_sync(0xFFFFFFFFu, s, off);
        q += __shfl_xor_sync(0xFFFFFFFFu, q, off);
    }
    float mean = s * (1.f / CDIM);
    float var  = q * (1.f / CDIM) - mean * mean;
    float rstd = rsqrtf(var + 1e-5f);
    uint2* dst = (uint2*)(out + (size_t)p * CDIM);
#pragma unroll
    for (int i = 0; i < 4; ++i) {
        int idx = lane + 32 * i;
        float4 gg = ((const float4*)gamma)[idx];
        float4 bb = ((const float4*)beta)[idx];
        float ox = (v[i].x - mean) * rstd * gg.x + bb.x;
        float oy = (v[i].y - mean) * rstd * gg.y + bb.y;
        float oz = (v[i].z - mean) * rstd * gg.z + bb.z;
        float ow = (v[i].w - mean) * rstd * gg.w + bb.w;
        __half2 h0 = __floats2half2_rn(ox, oy);
        __half2 h1 = __floats2half2_rn(oz, ow);
        uint2 u;
        u.x = *(uint32_t*)&h0;
        u.y = *(uint32_t*)&h1;
        dst[idx] = u;
    }
}

// ---------------- fp16 mma GEMM NT: 128x128 CTA, BK=64, swizzled smem (R12 config) ----------------
// 4 warps 2x2, warp tile 64x64, 3-stage cp.async, 2 CTAs/SM.
#define BKH 64
#define STAGE_B 32768
#define B_OFF 16384
#define NSTAGE 3
#define TG_SMEM (NSTAGE * STAGE_B)

template<int MODE>
__global__ __launch_bounds__(128, 2)
void tgemm(const __half* __restrict__ A, int lda,
           const __half* __restrict__ B, int ldb,
           const float* __restrict__ bias,
           void* __restrict__ Cv, int ldc, int K,
           const float* __restrict__ res) {
    extern __shared__ __half smh[];
    uint32_t sb = smem_u32(smh);

    int tid = threadIdx.x;
    int wid = tid >> 5, lane = tid & 31;
    int g   = lane >> 2;
    int tig = lane & 3;
    int hh  = lane >> 4;
    int warp_row = wid >> 1;
    int warp_col = wid & 1;

    const __half* Ag = A + (size_t)(blockIdx.y * 128) * lda;
    const __half* Bg = B + (size_t)(blockIdx.x * 128) * ldb;

    int cr[8], cc_[8], csw[8];
#pragma unroll
    for (int i = 0; i < 8; ++i) {
        int task = i * 128 + tid;
        cr[i]  = task >> 3;
        cc_[i] = task & 7;
        csw[i] = (cc_[i] ^ (cr[i] & 7)) << 4;
    }

    uint32_t abase[4], bbase[4];
    int a7[4], b7[4];
#pragma unroll
    for (int mt = 0; mt < 4; ++mt) {
        int row = warp_row * 64 + mt * 16 + (lane & 15);
        abase[mt] = (uint32_t)(row * 128);
        a7[mt] = row & 7;
    }
#pragma unroll
    for (int p = 0; p < 4; ++p) {
        int row = warp_col * 64 + p * 16 + (lane & 15);
        bbase[p] = (uint32_t)(B_OFF + row * 128);
        b7[p] = row & 7;
    }

    float acc[4][8][4];
#pragma unroll
    for (int mt = 0; mt < 4; ++mt)
#pragma unroll
        for (int nt = 0; nt < 8; ++nt)
#pragma unroll
            for (int j = 0; j < 4; ++j) acc[mt][nt][j] = 0.f;

    int ntiles = K / BKH;

#pragma unroll
    for (int s = 0; s < 2; ++s) {
        int k0 = s * BKH;
        uint32_t st = sb + s * STAGE_B;
#pragma unroll
        for (int i = 0; i < 8; ++i) {
            CP_ASYNC16(st + cr[i] * 128 + csw[i],
                       Ag + (size_t)cr[i] * lda + k0 + cc_[i] * 8);
            CP_ASYNC16(st + B_OFF + cr[i] * 128 + csw[i],
                       Bg + (size_t)cr[i] * ldb + k0 + cc_[i] * 8);
        }
        CP_COMMIT();
    }

    int stage = 0;
    for (int t = 0; t < ntiles; ++t) {
        CP_WAIT(1);
        __syncthreads();
        if (t + 2 < ntiles) {
            int k0 = (t + 2) * BKH;
            int s2 = stage + 2; if (s2 >= NSTAGE) s2 -= NSTAGE;
            uint32_t st = sb + s2 * STAGE_B;
#pragma unroll
            for (int i = 0; i < 8; ++i) {
                CP_ASYNC16(st + cr[i] * 128 + csw[i],
                           Ag + (size_t)cr[i] * lda + k0 + cc_[i] * 8);
                CP_ASYNC16(st + B_OFF + cr[i] * 128 + csw[i],
                           Bg + (size_t)cr[i] * ldb + k0 + cc_[i] * 8);
            }
        }
        CP_COMMIT();

        uint32_t sbase = sb + stage * STAGE_B;
#pragma unroll
        for (int ks = 0; ks < 4; ++ks) {
            int cc2 = ks * 2 + hh;
            uint32_t af[4][4], bf[4][4];
#pragma unroll
            for (int mt = 0; mt < 4; ++mt)
                LDSM4(af[mt], sbase + abase[mt] + (uint32_t)((cc2 ^ a7[mt]) << 4));
#pragma unroll
            for (int p = 0; p < 4; ++p)
                LDSM4(bf[p], sbase + bbase[p] + (uint32_t)((cc2 ^ b7[p]) << 4));
#pragma unroll
            for (int mt = 0; mt < 4; ++mt)
#pragma unroll
                for (int p = 0; p < 4; ++p) {
                    mma_f16(acc[mt][2 * p + 0], af[mt], bf[p][0], bf[p][2]);
                    mma_f16(acc[mt][2 * p + 1], af[mt], bf[p][1], bf[p][3]);
                }
        }
        if (++stage >= NSTAGE) stage -= NSTAGE;
    }

    int gr_base = blockIdx.y * 128 + warp_row * 64;
    int gc_base = blockIdx.x * 128 + warp_col * 64;

    __half* Ch = (__half*)Cv;
    float*  Cf = (float*)Cv;

#pragma unroll
    for (int mt = 0; mt < 4; ++mt) {
#pragma unroll
        for (int hf = 0; hf < 2; ++hf) {
            int gr = gr_base + mt * 16 + g + hf * 8;
            size_t crow = (MODE == 1) ? win_row_to_flat(gr) * (size_t)ldc : (size_t)gr * ldc;
#pragma unroll
            for (int nt = 0; nt < 8; ++nt) {
                int col = gc_base + nt * 8 + tig * 2;
                float2 bs = *(const float2*)&bias[col];
                float v0 = acc[mt][nt][hf * 2 + 0] + bs.x;
                float v1 = acc[mt][nt][hf * 2 + 1] + bs.y;
                if (MODE == 2) {
                    // gelu(x) ~= x * sigmoid(1.595769122*x + 0.071354816*x^3)
                    float y0 = v0 * (1.595769122f + 0.071354816f * v0 * v0);
                    float y1 = v1 * (1.595769122f + 0.071354816f * v1 * v1);
                    v0 = v0 / (1.f + __expf(-y0));
                    v1 = v1 / (1.f + __expf(-y1));
                }
                if (MODE == 1 || MODE == 3) {
                    float2 rr = *(const float2*)&res[crow + col];
                    v0 += rr.x; v1 += rr.y;
                    *(float2*)&Cf[crow + col] = make_float2(v0, v1);
                } else {
                    __half2 hv = __floats2half2_rn(v0, v1);
                    *(__half2*)&Ch[crow + col] = hv;
                }
            }
        }
    }
}

// ---------------- tensor-core windowed attention: 1 warp per (window, head) ----------------
__global__ __launch_bounds__(128)
void attn_kernel(__half* __restrict__ qkv, const float* __restrict__ pbm) {
    __shared__ __align__(16) uint8_t sm[49152];

    int tid = threadIdx.x, wid = tid >> 5, lane = tid & 31;
    int gid = blockIdx.x * 4 + wid;
    int win = gid >> 4, h = gid & 15;
    int wl  = win % NWIN;
    int wh  = wl / NWH;
    int ww  = wl - wh * NWH;
    int cls = ((wh == 6) ? 2 : 0) + ((ww == 6) ? 1 : 0);

    uint8_t* wsm = sm + wid * 12288;
    uint32_t sbase = smem_u32(wsm);
    const float scale = 0.17677669529663687f;

    for (int i = lane; i < 256; i += 32) {
        int row = i >> 2, c = i & 3;
        size_t gbase = (size_t)(win * NTOK + row) * QKVC + h * HDIM + c * 8;
        uint4 qu = *(const uint4*)(qkv + gbase);
        uint4 ku = *(const uint4*)(qkv + gbase + CDIM);
        uint4 vu = *(const uint4*)(qkv + gbase + 2 * CDIM);
        int sw = row * 64 + ((c ^ ((row >> 1) & 3)) << 4);
        *(uint4*)(wsm + sw)         = qu;
        *(uint4*)(wsm + 4096 + sw)  = ku;
        *(uint4*)(wsm + 8192 + sw)  = vu;
    }
    __syncwarp();

    float acc[4][8][4];
#pragma unroll
    for (int mt = 0; mt < 4; ++mt)
#pragma unroll
        for (int nt = 0; nt < 8; ++nt)
#pragma unroll
            for (int j = 0; j < 4; ++j) acc[mt][nt][j] = 0.f;

#pragma unroll
    for (int ks = 0; ks < 2; ++ks) {
        uint32_t af[4][4], bf[4][4];
#pragma unroll
        for (int mt = 0; mt < 4; ++mt) {
            int row = mt * 16 + (lane & 15);
            int ch = (ks * 2 + (lane >> 4)) ^ ((row >> 1) & 3);
            LDSM4(af[mt], sbase + row * 64 + (ch << 4));
        }
#pragma unroll
        for (int p = 0; p < 4; ++p) {
            int row = p * 16 + (lane & 15);
            int ch = (ks * 2 + (lane >> 4)) ^ ((row >> 1) & 3);
            LDSM4(bf[p], sbase + 4096 + row * 64 + (ch << 4));
        }
#pragma unroll
        for (int mt = 0; mt < 4; ++mt)
#pragma unroll
            for (int p = 0; p < 4; ++p) {
                mma_f16(acc[mt][2 * p + 0], af[mt], bf[p][0], bf[p][2]);
                mma_f16(acc[mt][2 * p + 1], af[mt], bf[p][1], bf[p][3]);
            }
    }

    const float* pbb = pbm + (size_t)(cls * NH + h) * 4096;
    float inv_[4][2];
#pragma unroll
    for (int mt = 0; mt < 4; ++mt) {
#pragma unroll
        for (int hf = 0; hf < 2; ++hf) {
            int qc = mt * 2 + hf;
            float s[16];
            float mx = -1e30f;
#pragma unroll
            for (int f4 = 0; f4 < 4; ++f4) {
                float4 pv = *(const float4*)&pbb[((qc * 4 + f4) * 32 + lane) * 4];
                float pe[4] = {pv.x, pv.y, pv.z, pv.w};
#pragma unroll
                for (int e = 0; e < 4; ++e) {
                    int nt = f4 * 2 + (e >> 1), j = e & 1;
                    float v = acc[mt][nt][hf * 2 + j] * scale + pe[e];
                    s[f4 * 4 + e] = v;
                    mx = fmaxf(mx, v);
                }
            }
            mx = fmaxf(mx, __shfl_xor_sync(0xFFFFFFFFu, mx, 1));
            mx = fmaxf(mx, __shfl_xor_sync(0xFFFFFFFFu, mx, 2));
            float sum = 0.f;
#pragma unroll
            for (int i = 0; i < 16; ++i) {
                float e_ = __expf(s[i] - mx);
                s[i] = e_;
                sum += e_;
            }
            sum += __shfl_xor_sync(0xFFFFFFFFu, sum, 1);
            sum += __shfl_xor_sync(0xFFFFFFFFu, sum, 2);
            inv_[mt][hf] = 1.f / sum;
#pragma unroll
            for (int f4 = 0; f4 < 4; ++f4)
#pragma unroll
                for (int e = 0; e < 4; ++e)
                    acc[mt][f4 * 2 + (e >> 1)][hf * 2 + (e & 1)] = s[f4 * 4 + e];
        }
    }

    uint32_t ph[4][4][4];
#pragma unroll
    for (int mt = 0; mt < 4; ++mt)
#pragma unroll
        for (int ks = 0; ks < 4; ++ks) {
            __half2 h0 = __floats2half2_rn(acc[mt][2 * ks][0], acc[mt][2 * ks][1]);
            __half2 h1 = __floats2half2_rn(acc[mt][2 * ks][2], acc[mt][2 * ks][3]);
            __half2 h2 = __floats2half2_rn(acc[mt][2 * ks + 1][0], acc[mt][2 * ks + 1][1]);
            __half2 h3 = __floats2half2_rn(acc[mt][2 * ks + 1][2], acc[mt][2 * ks + 1][3]);
            ph[mt][ks][0] = *(uint32_t*)&h0;
            ph[mt][ks][1] = *(uint32_t*)&h1;
            ph[mt][ks][2] = *(uint32_t*)&h2;
            ph[mt][ks][3] = *(uint32_t*)&h3;
        }

    float oacc[4][4][4];
#pragma unroll
    for (int mt = 0; mt < 4; ++mt)
#pragma unroll
        for (int nt = 0; nt < 4; ++nt)
#pragma unroll
            for (int j = 0; j < 4; ++j) oacc[mt][nt][j] = 0.f;

#pragma unroll
    for (int ks = 0; ks < 4; ++ks) {
        int token = ks * 16 + (lane & 15);
        int chA = (0 + (lane >> 4)) ^ ((token >> 1) & 3);
        int chB = (2 + (lane >> 4)) ^ ((token >> 1) & 3);
        uint32_t vfa[4], vfb[4];
        LDSM4T(vfa, sbase + 8192 + token * 64 + (chA << 4));
        LDSM4T(vfb, sbase + 8192 + token * 64 + (chB << 4));
#pragma unroll
        for (int mt = 0; mt < 4; ++mt) {
            mma_f16(oacc[mt][0], ph[mt][ks], vfa[0], vfa[1]);
            mma_f16(oacc[mt][1], ph[mt][ks], vfa[2], vfa[3]);
            mma_f16(oacc[mt][2], ph[mt][ks], vfb[0], vfb[1]);
            mma_f16(oacc[mt][3], ph[mt][ks], vfb[2], vfb[3]);
        }
    }

    int g = lane >> 2, tig = lane & 3;
#pragma unroll
    for (int mt = 0; mt < 4; ++mt) {
#pragma unroll
        for (int hf = 0; hf < 2; ++hf) {
            int t = mt * 16 + g + 8 * hf;
            float inv = inv_[mt][hf];
            size_t ob = (size_t)(win * NTOK + t) * QKVC + h * HDIM;
#pragma unroll
            for (int nt = 0; nt < 4; ++nt) {
                int d = nt * 8 + tig * 2;
                __half2 hv = __floats2half2_rn(oacc[mt][nt][hf * 2] * inv,
                                               oacc[mt][nt][hf * 2 + 1] * inv);
                *(__half2*)(qkv + ob + d) = hv;
            }
        }
    }
}

// ---------------- launch ----------------
extern "C" void kernel_launch(void* const* d_in, const int* in_sizes, int n_in,
                              void* d_out, int out_size) {
    const float* x      = (const float*)d_in[0];
    const float* g1     = (const float*)d_in[1];
    const float* be1    = (const float*)d_in[2];
    const float* w_qkv  = (const float*)d_in[3];
    const float* b_qkv  = (const float*)d_in[4];
    const float* pm_w1  = (const float*)d_in[5];
    const float* pm_b1  = (const float*)d_in[6];
    const float* pm_w2  = (const float*)d_in[7];
    const float* pm_b2  = (const float*)d_in[8];
    const float* w_proj = (const float*)d_in[9];
    const float* b_proj = (const float*)d_in[10];
    const float* g2     = (const float*)d_in[11];
    const float* be2    = (const float*)d_in[12];
    const float* w_fc1  = (const float*)d_in[13];
    const float* b_fc1  = (const float*)d_in[14];
    const float* w_fc2  = (const float*)d_in[15];
    const float* b_fc2  = (const float*)d_in[16];
    float* out = (float*)d_out;

    __half *p_xw, *p_qkv, *p_hidden, *p_wh;
    float *p_x1, *p_pbm;
    cudaGetSymbolAddress((void**)&p_xw, g_xw);
    cudaGetSymbolAddress((void**)&p_qkv, g_qkv);
    cudaGetSymbolAddress((void**)&p_x1, g_x1);
    cudaGetSymbolAddress((void**)&p_hidden, g_hidden);
    cudaGetSymbolAddress((void**)&p_wh, g_wh);
    cudaGetSymbolAddress((void**)&p_pbm, g_pbm);

    cudaFuncSetAttribute(tgemm<0>, cudaFuncAttributeMaxDynamicSharedMemorySize, TG_SMEM);
    cudaFuncSetAttribute(tgemm<1>, cudaFuncAttributeMaxDynamicSharedMemorySize, TG_SMEM);
    cudaFuncSetAttribute(tgemm<2>, cudaFuncAttributeMaxDynamicSharedMemorySize, TG_SMEM);
    cudaFuncSetAttribute(tgemm<3>, cudaFuncAttributeMaxDynamicSharedMemorySize, TG_SMEM);

    // 0. weight conversion + pos-bias fragment tables
    cvtw_kernel<<<WTOT / 4 / 256, 256>>>(w_qkv, w_proj, w_fc1, w_fc2);
    posbias_kernel<<<4 * NH, 256>>>(pm_w1, pm_b1, pm_w2, pm_b2);

    // 1. LN1 + shifted-window gather -> g_xw (fp16)
    ln_kernel<<<MROWS / 8, 256>>>(x, g1, be1, p_xw, 1);

    // 2. QKV GEMM -> g_qkv (fp16)
    tgemm<0><<<dim3(QKVC / 128, MROWS / 128), 128, TG_SMEM>>>(
        p_xw, CDIM, p_wh + WQ_OFF, CDIM, b_qkv, p_qkv, QKVC, CDIM, nullptr);

    // 3. tensor-core windowed attention (writes into q-region)
    attn_kernel<<<NWTOT * NH / 4, 128>>>(p_qkv, p_pbm);

    // 4. proj GEMM + window-reverse scatter + residual -> g_x1 (fp32)
    tgemm<1><<<dim3(CDIM / 128, MROWS / 128), 128, TG_SMEM>>>(
        p_qkv, QKVC, p_wh + WP_OFF, CDIM, b_proj, p_x1, CDIM, CDIM, x);

    // 5. LN2 -> g_xw (fp16)
    ln_kernel<<<MROWS / 8, 256>>>(p_x1, g2, be2, p_xw, 0);

    // 6. FC1 + GELU(sigmoid form) -> g_hidden (fp16)
    tgemm<2><<<dim3(HID / 128, MROWS / 128), 128, TG_SMEM>>>(
        p_xw, CDIM, p_wh + W1_OFF, CDIM, b_fc1, p_hidden, HID, CDIM, nullptr);

    // 7. FC2 + residual -> d_out (fp32)
    tgemm<3><<<dim3(CDIM / 128, MROWS / 128), 128, TG_SMEM>>>(
        p_hidden, HID, p_wh + W2_OFF, HID, b_fc2, out, CDIM, HID, p_x1);
}

// round 15
// speedup vs baseline: 1.0224x; 1.0224x over previous
#include <cuda_runtime.h>
#include <cuda_fp16.h>
#include <math.h>
#include <cstdint>

// ---------------- problem constants ----------------
#define BB    32
#define HH    56
#define WWI   56
#define LTOK  3136          // 56*56
#define CDIM  512
#define NH    16
#define HDIM  32
#define WSZ   8
#define NTOK  64            // 8*8
#define SHFT  4
#define NWH   7
#define NWIN  49            // 7*7
#define NWTOT 1568          // BB*NWIN
#define MROWS 100352        // BB*LTOK = NWTOT*NTOK
#define HID   2048
#define QKVC  1536

// weight offsets in g_wh (halves)
#define WQ_OFF  0
#define WP_OFF  786432            // 1536*512
#define W1_OFF  1048576           // + 512*512
#define W2_OFF  2097152           // + 2048*512
#define WTOT    3145728           // + 512*2048

// ---------------- static device scratch ----------------
__device__ __half g_xw[(size_t)MROWS * CDIM];      // LN outputs (fp16)
__device__ __half g_qkv[(size_t)MROWS * QKVC];     // qkv fp16; q-region reused as attn out
__device__ float  g_x1[(size_t)MROWS * CDIM];      // residual after attention (fp32)
__device__ __half g_hidden[(size_t)MROWS * HID];   // MLP hidden fp16
__device__ __half g_wh[WTOT];                      // fp16 weights
__device__ float  g_pbm[4 * NH * 4096];            // pos-bias + mask, fragment layout

// ---------------- helpers ----------------
__device__ __forceinline__ uint32_t smem_u32(const void* p) {
    uint32_t a;
    asm("{ .reg .u64 t; cvta.to.shared.u64 t, %1; cvt.u32.u64 %0, t; }" : "=r"(a) : "l"(p));
    return a;
}
#define CP_ASYNC16(dst, src) \
    asm volatile("cp.async.cg.shared.global [%0], [%1], 16;" :: "r"(dst), "l"(src))
#define CP_COMMIT() asm volatile("cp.async.commit_group;" ::: "memory")
#define CP_WAIT(n)  asm volatile("cp.async.wait_group %0;" :: "n"(n) : "memory")

#define LDSM4(r, addr) \
    asm volatile("ldmatrix.sync.aligned.m8n8.x4.shared.b16 {%0,%1,%2,%3}, [%4];" \
        : "=r"((r)[0]), "=r"((r)[1]), "=r"((r)[2]), "=r"((r)[3]) : "r"(addr))
#define LDSM4T(r, addr) \
    asm volatile("ldmatrix.sync.aligned.m8n8.x4.trans.shared.b16 {%0,%1,%2,%3}, [%4];" \
        : "=r"((r)[0]), "=r"((r)[1]), "=r"((r)[2]), "=r"((r)[3]) : "r"(addr))

__device__ __forceinline__ void mma_f16(float* d, const uint32_t* a, uint32_t b0, uint32_t b1) {
    asm volatile(
        "mma.sync.aligned.m16n8k16.row.col.f32.f16.f16.f32 "
        "{%0,%1,%2,%3}, {%4,%5,%6,%7}, {%8,%9}, {%0,%1,%2,%3};"
        : "+f"(d[0]), "+f"(d[1]), "+f"(d[2]), "+f"(d[3])
        : "r"(a[0]), "r"(a[1]), "r"(a[2]), "r"(a[3]), "r"(b0), "r"(b1));
}

// windowed row p -> flat row in original (B, H*W) layout
__device__ __forceinline__ size_t win_row_to_flat(int p) {
    int b   = p / LTOK;
    int rem = p - b * LTOK;
    int wl  = rem >> 6;
    int t   = rem & 63;
    int wh  = wl / NWH;
    int ww  = wl - wh * NWH;
    int r   = (wh * WSZ + (t >> 3) + SHFT) % HH;
    int c   = (ww * WSZ + (t & 7)  + SHFT) % WWI;
    return (size_t)b * LTOK + (size_t)r * WWI + c;
}

// ---------------- weight fp32 -> fp16 conversion ----------------
__global__ __launch_bounds__(256)
void cvtw_kernel(const float* __restrict__ wq, const float* __restrict__ wp,
                 const float* __restrict__ w1, const float* __restrict__ w2) {
    int i4 = (blockIdx.x * 256 + threadIdx.x) * 4;
    const float* src;
    int off;
    if      (i4 < WP_OFF) { src = wq; off = i4; }
    else if (i4 < W1_OFF) { src = wp; off = i4 - WP_OFF; }
    else if (i4 < W2_OFF) { src = w1; off = i4 - W1_OFF; }
    else                  { src = w2; off = i4 - W2_OFF; }
    float4 v = *(const float4*)(src + off);
    __half2 a = __floats2half2_rn(v.x, v.y);
    __half2 b = __floats2half2_rn(v.z, v.w);
    uint2 u;
    u.x = *(uint32_t*)&a;
    u.y = *(uint32_t*)&b;
    *(uint2*)&g_wh[i4] = u;
}

// ---------------- pos-bias + mask table, fragment layout ----------------
__global__ __launch_bounds__(256)
void posbias_kernel(const float* __restrict__ w1, const float* __restrict__ b1,
                    const float* __restrict__ w2, const float* __restrict__ b2) {
    int blk = blockIdx.x;            // cls*16 + h
    int cls = blk >> 4, h = blk & 15;
    int rh = cls >> 1, rw = cls & 1;
    for (int f = threadIdx.x; f < 1024; f += 256) {
        int lane = f & 31, f4 = (f >> 5) & 3, qc = f >> 7;
        int mt = qc >> 1, hf = qc & 1, g = lane >> 2, tig = lane & 3;
        int n = mt * 16 + g + 8 * hf;           // query token
        float out[4];
#pragma unroll
        for (int e = 0; e < 4; ++e) {
            int nt = f4 * 2 + (e >> 1), j = e & 1;
            int m = nt * 8 + tig * 2 + j;       // key token
            float dh = (float)((n >> 3) - (m >> 3));
            float dw = (float)((n & 7) - (m & 7));
            float fh = (dh > 0.f) ? log1pf(dh) : ((dh < 0.f) ? -log1pf(-dh) : 0.f);
            float fw = (dw > 0.f) ? log1pf(dw) : ((dw < 0.f) ? -log1pf(-dw) : 0.f);
            float acc = b2[h];
#pragma unroll
            for (int o = 0; o < 32; ++o) {
                float hv = fmaxf(w1[2 * o] * fh + w1[2 * o + 1] * fw + b1[o], 0.f);
                acc += w2[h * 32 + o] * hv;
            }
            int gin = rh ? (((n >> 3) < 4) ? 1 : 2) : 0;
            int gjn = rw ? (((n & 7) < 4) ? 1 : 2) : 0;
            int gim = rh ? (((m >> 3) < 4) ? 1 : 2) : 0;
            int gjm = rw ? (((m & 7) < 4) ? 1 : 2) : 0;
            if (gin != gim || gjn != gjm) acc -= 100.f;
            out[e] = acc;
        }
        *(float4*)&g_pbm[(size_t)blk * 4096 + f * 4] = make_float4(out[0], out[1], out[2], out[3]);
    }
}

// ---------------- LayerNorm: warp-per-row, fp32 in, fp16 out ----------------
__global__ __launch_bounds__(256)
void ln_kernel(const float* __restrict__ in, const float* __restrict__ gamma,
               const float* __restrict__ beta, __half* __restrict__ out, int gather) {
    int warp = threadIdx.x >> 5, lane = threadIdx.x & 31;
    int p = blockIdx.x * 8 + warp;
    size_t srow = gather ? win_row_to_flat(p) : (size_t)p;
    const float4* src = (const float4*)(in + srow * CDIM);
    float4 v[4];
#pragma unroll
    for (int i = 0; i < 4; ++i) v[i] = src[lane + 32 * i];
    float s = 0.f, q = 0.f;
#pragma unroll
    for (int i = 0; i < 4; ++i) {
        s += v[i].x + v[i].y + v[i].z + v[i].w;
        q += v[i].x * v[i].x + v[i].y * v[i].y + v[i].z * v[i].z + v[i].w * v[i].w;
    }
#pragma unroll
    for (int off = 16; off > 0; off >>= 1) {
        s += __shfl_xor_sync(0xFFFFFFFFu, s, off);
        q += __shfl_xor_sync(0xFFFFFFFFu, q, off);
    }
    float mean = s * (1.f / CDIM);
    float var  = q * (1.f / CDIM) - mean * mean;
    float rstd = rsqrtf(var + 1e-5f);
    uint2* dst = (uint2*)(out + (size_t)p * CDIM);
#pragma unroll
    for (int i = 0; i < 4; ++i) {
        int idx = lane + 32 * i;
        float4 gg = ((const float4*)gamma)[idx];
        float4 bb = ((const float4*)beta)[idx];
        float ox = (v[i].x - mean) * rstd * gg.x + bb.x;
        float oy = (v[i].y - mean) * rstd * gg.y + bb.y;
        float oz = (v[i].z - mean) * rstd * gg.z + bb.z;
        float ow = (v[i].w - mean) * rstd * gg.w + bb.w;
        __half2 h0 = __floats2half2_rn(ox, oy);
        __half2 h1 = __floats2half2_rn(oz, ow);
        uint2 u;
        u.x = *(uint32_t*)&h0;
        u.y = *(uint32_t*)&h1;
        dst[idx] = u;
    }
}

// ---------------- fp16 mma GEMM NT: 128x128 CTA, BK=64, swizzled smem (R12 config) ----------------
// 4 warps 2x2, warp tile 64x64, 3-stage cp.async, 2 CTAs/SM.
#define BKH 64
#define STAGE_B 32768
#define B_OFF 16384
#define NSTAGE 3
#define TG_SMEM (NSTAGE * STAGE_B)

template<int MODE>
__global__ __launch_bounds__(128, 2)
void tgemm(const __half* __restrict__ A, int lda,
           const __half* __restrict__ B, int ldb,
           const float* __restrict__ bias,
           void* __restrict__ Cv, int ldc, int K,
           const float* __restrict__ res) {
    extern __shared__ __half smh[];
    uint32_t sb = smem_u32(smh);

    int tid = threadIdx.x;
    int wid = tid >> 5, lane = tid & 31;
    int g   = lane >> 2;
    int tig = lane & 3;
    int hh  = lane >> 4;
    int warp_row = wid >> 1;
    int warp_col = wid & 1;

    const __half* Ag = A + (size_t)(blockIdx.y * 128) * lda;
    const __half* Bg = B + (size_t)(blockIdx.x * 128) * ldb;

    int cr[8], cc_[8], csw[8];
#pragma unroll
    for (int i = 0; i < 8; ++i) {
        int task = i * 128 + tid;
        cr[i]  = task >> 3;
        cc_[i] = task & 7;
        csw[i] = (cc_[i] ^ (cr[i] & 7)) << 4;
    }

    uint32_t abase[4], bbase[4];
    int a7[4], b7[4];
#pragma unroll
    for (int mt = 0; mt < 4; ++mt) {
        int row = warp_row * 64 + mt * 16 + (lane & 15);
        abase[mt] = (uint32_t)(row * 128);
        a7[mt] = row & 7;
    }
#pragma unroll
    for (int p = 0; p < 4; ++p) {
        int row = warp_col * 64 + p * 16 + (lane & 15);
        bbase[p] = (uint32_t)(B_OFF + row * 128);
        b7[p] = row & 7;
    }

    float acc[4][8][4];
#pragma unroll
    for (int mt = 0; mt < 4; ++mt)
#pragma unroll
        for (int nt = 0; nt < 8; ++nt)
#pragma unroll
            for (int j = 0; j < 4; ++j) acc[mt][nt][j] = 0.f;

    int ntiles = K / BKH;

#pragma unroll
    for (int s = 0; s < 2; ++s) {
        int k0 = s * BKH;
        uint32_t st = sb + s * STAGE_B;
#pragma unroll
        for (int i = 0; i < 8; ++i) {
            CP_ASYNC16(st + cr[i] * 128 + csw[i],
                       Ag + (size_t)cr[i] * lda + k0 + cc_[i] * 8);
            CP_ASYNC16(st + B_OFF + cr[i] * 128 + csw[i],
                       Bg + (size_t)cr[i] * ldb + k0 + cc_[i] * 8);
        }
        CP_COMMIT();
    }

    int stage = 0;
    for (int t = 0; t < ntiles; ++t) {
        CP_WAIT(1);
        __syncthreads();
        if (t + 2 < ntiles) {
            int k0 = (t + 2) * BKH;
            int s2 = stage + 2; if (s2 >= NSTAGE) s2 -= NSTAGE;
            uint32_t st = sb + s2 * STAGE_B;
#pragma unroll
            for (int i = 0; i < 8; ++i) {
                CP_ASYNC16(st + cr[i] * 128 + csw[i],
                           Ag + (size_t)cr[i] * lda + k0 + cc_[i] * 8);
                CP_ASYNC16(st + B_OFF + cr[i] * 128 + csw[i],
                           Bg + (size_t)cr[i] * ldb + k0 + cc_[i] * 8);
            }
        }
        CP_COMMIT();

        uint32_t sbase = sb + stage * STAGE_B;
#pragma unroll
        for (int ks = 0; ks < 4; ++ks) {
            int cc2 = ks * 2 + hh;
            uint32_t af[4][4], bf[4][4];
#pragma unroll
            for (int mt = 0; mt < 4; ++mt)
                LDSM4(af[mt], sbase + abase[mt] + (uint32_t)((cc2 ^ a7[mt]) << 4));
#pragma unroll
            for (int p = 0; p < 4; ++p)
                LDSM4(bf[p], sbase + bbase[p] + (uint32_t)((cc2 ^ b7[p]) << 4));
#pragma unroll
            for (int mt = 0; mt < 4; ++mt)
#pragma unroll
                for (int p = 0; p < 4; ++p) {
                    mma_f16(acc[mt][2 * p + 0], af[mt], bf[p][0], bf[p][2]);
                    mma_f16(acc[mt][2 * p + 1], af[mt], bf[p][1], bf[p][3]);
                }
        }
        if (++stage >= NSTAGE) stage -= NSTAGE;
    }

    int gr_base = blockIdx.y * 128 + warp_row * 64;
    int gc_base = blockIdx.x * 128 + warp_col * 64;

    __half* Ch = (__half*)Cv;
    float*  Cf = (float*)Cv;

#pragma unroll
    for (int mt = 0; mt < 4; ++mt) {
#pragma unroll
        for (int hf = 0; hf < 2; ++hf) {
            int gr = gr_base + mt * 16 + g + hf * 8;
            size_t crow = (MODE == 1) ? win_row_to_flat(gr) * (size_t)ldc : (size_t)gr * ldc;
#pragma unroll
            for (int nt = 0; nt < 8; ++nt) {
                int col = gc_base + nt * 8 + tig * 2;
                float2 bs = *(const float2*)&bias[col];
                float v0 = acc[mt][nt][hf * 2 + 0] + bs.x;
                float v1 = acc[mt][nt][hf * 2 + 1] + bs.y;
                if (MODE == 2) {
                    v0 = 0.5f * v0 * (1.0f + erff(v0 * 0.70710678118654752f));
                    v1 = 0.5f * v1 * (1.0f + erff(v1 * 0.70710678118654752f));
                }
                if (MODE == 1 || MODE == 3) {
                    float2 rr = *(const float2*)&res[crow + col];
                    v0 += rr.x; v1 += rr.y;
                    *(float2*)&Cf[crow + col] = make_float2(v0, v1);
                } else {
                    __half2 hv = __floats2half2_rn(v0, v1);
                    *(__half2*)&Ch[crow + col] = hv;
                }
            }
        }
    }
}

// ---------------- tensor-core windowed attention: 1 warp per (window, head) ----------------
__global__ __launch_bounds__(128)
void attn_kernel(__half* __restrict__ qkv, const float* __restrict__ pbm) {
    __shared__ __align__(16) uint8_t sm[49152];

    int tid = threadIdx.x, wid = tid >> 5, lane = tid & 31;
    int gid = blockIdx.x * 4 + wid;
    int win = gid >> 4, h = gid & 15;
    int wl  = win % NWIN;
    int wh  = wl / NWH;
    int ww  = wl - wh * NWH;
    int cls = ((wh == 6) ? 2 : 0) + ((ww == 6) ? 1 : 0);

    uint8_t* wsm = sm + wid * 12288;
    uint32_t sbase = smem_u32(wsm);
    const float scale = 0.17677669529663687f;

    for (int i = lane; i < 256; i += 32) {
        int row = i >> 2, c = i & 3;
        size_t gbase = (size_t)(win * NTOK + row) * QKVC + h * HDIM + c * 8;
        uint4 qu = *(const uint4*)(qkv + gbase);
        uint4 ku = *(const uint4*)(qkv + gbase + CDIM);
        uint4 vu = *(const uint4*)(qkv + gbase + 2 * CDIM);
        int sw = row * 64 + ((c ^ ((row >> 1) & 3)) << 4);
        *(uint4*)(wsm + sw)         = qu;
        *(uint4*)(wsm + 4096 + sw)  = ku;
        *(uint4*)(wsm + 8192 + sw)  = vu;
    }
    __syncwarp();

    float acc[4][8][4];
#pragma unroll
    for (int mt = 0; mt < 4; ++mt)
#pragma unroll
        for (int nt = 0; nt < 8; ++nt)
#pragma unroll
            for (int j = 0; j < 4; ++j) acc[mt][nt][j] = 0.f;

#pragma unroll
    for (int ks = 0; ks < 2; ++ks) {
        uint32_t af[4][4], bf[4][4];
#pragma unroll
        for (int mt = 0; mt < 4; ++mt) {
            int row = mt * 16 + (lane & 15);
            int ch = (ks * 2 + (lane >> 4)) ^ ((row >> 1) & 3);
            LDSM4(af[mt], sbase + row * 64 + (ch << 4));
        }
#pragma unroll
        for (int p = 0; p < 4; ++p) {
            int row = p * 16 + (lane & 15);
            int ch = (ks * 2 + (lane >> 4)) ^ ((row >> 1) & 3);
            LDSM4(bf[p], sbase + 4096 + row * 64 + (ch << 4));
        }
#pragma unroll
        for (int mt = 0; mt < 4; ++mt)
#pragma unroll
            for (int p = 0; p < 4; ++p) {
                mma_f16(acc[mt][2 * p + 0], af[mt], bf[p][0], bf[p][2]);
                mma_f16(acc[mt][2 * p + 1], af[mt], bf[p][1], bf[p][3]);
            }
    }

    const float* pbb = pbm + (size_t)(cls * NH + h) * 4096;
    float inv_[4][2];
#pragma unroll
    for (int mt = 0; mt < 4; ++mt) {
#pragma unroll
        for (int hf = 0; hf < 2; ++hf) {
            int qc = mt * 2 + hf;
            float s[16];
            float mx = -1e30f;
#pragma unroll
            for (int f4 = 0; f4 < 4; ++f4) {
                float4 pv = *(const float4*)&pbb[((qc * 4 + f4) * 32 + lane) * 4];
                float pe[4] = {pv.x, pv.y, pv.z, pv.w};
#pragma unroll
                for (int e = 0; e < 4; ++e) {
                    int nt = f4 * 2 + (e >> 1), j = e & 1;
                    float v = acc[mt][nt][hf * 2 + j] * scale + pe[e];
                    s[f4 * 4 + e] = v;
                    mx = fmaxf(mx, v);
                }
            }
            mx = fmaxf(mx, __shfl_xor_sync(0xFFFFFFFFu, mx, 1));
            mx = fmaxf(mx, __shfl_xor_sync(0xFFFFFFFFu, mx, 2));
            float sum = 0.f;
#pragma unroll
            for (int i = 0; i < 16; ++i) {
                float e_ = __expf(s[i] - mx);
                s[i] = e_;
                sum += e_;
            }
            sum += __shfl_xor_sync(0xFFFFFFFFu, sum, 1);
            sum += __shfl_xor_sync(0xFFFFFFFFu, sum, 2);
            inv_[mt][hf] = 1.f / sum;
#pragma unroll
            for (int f4 = 0; f4 < 4; ++f4)
#pragma unroll
                for (int e = 0; e < 4; ++e)
                    acc[mt][f4 * 2 + (e >> 1)][hf * 2 + (e & 1)] = s[f4 * 4 + e];
        }
    }

    uint32_t ph[4][4][4];
#pragma unroll
    for (int mt = 0; mt < 4; ++mt)
#pragma unroll
        for (int ks = 0; ks < 4; ++ks) {
            __half2 h0 = __floats2half2_rn(acc[mt][2 * ks][0], acc[mt][2 * ks][1]);
            __half2 h1 = __floats2half2_rn(acc[mt][2 * ks][2], acc[mt][2 * ks][3]);
            __half2 h2 = __floats2half2_rn(acc[mt][2 * ks + 1][0], acc[mt][2 * ks + 1][1]);
            __half2 h3 = __floats2half2_rn(acc[mt][2 * ks + 1][2], acc[mt][2 * ks + 1][3]);
            ph[mt][ks][0] = *(uint32_t*)&h0;
            ph[mt][ks][1] = *(uint32_t*)&h1;
            ph[mt][ks][2] = *(uint32_t*)&h2;
            ph[mt][ks][3] = *(uint32_t*)&h3;
        }

    float oacc[4][4][4];
#pragma unroll
    for (int mt = 0; mt < 4; ++mt)
#pragma unroll
        for (int nt = 0; nt < 4; ++nt)
#pragma unroll
            for (int j = 0; j < 4; ++j) oacc[mt][nt][j] = 0.f;

#pragma unroll
    for (int ks = 0; ks < 4; ++ks) {
        int token = ks * 16 + (lane & 15);
        int chA = (0 + (lane >> 4)) ^ ((token >> 1) & 3);
        int chB = (2 + (lane >> 4)) ^ ((token >> 1) & 3);
        uint32_t vfa[4], vfb[4];
        LDSM4T(vfa, sbase + 8192 + token * 64 + (chA << 4));
        LDSM4T(vfb, sbase + 8192 + token * 64 + (chB << 4));
#pragma unroll
        for (int mt = 0; mt < 4; ++mt) {
            mma_f16(oacc[mt][0], ph[mt][ks], vfa[0], vfa[1]);
            mma_f16(oacc[mt][1], ph[mt][ks], vfa[2], vfa[3]);
            mma_f16(oacc[mt][2], ph[mt][ks], vfb[0], vfb[1]);
            mma_f16(oacc[mt][3], ph[mt][ks], vfb[2], vfb[3]);
        }
    }

    int g = lane >> 2, tig = lane & 3;
#pragma unroll
    for (int mt = 0; mt < 4; ++mt) {
#pragma unroll
        for (int hf = 0; hf < 2; ++hf) {
            int t = mt * 16 + g + 8 * hf;
            float inv = inv_[mt][hf];
            size_t ob = (size_t)(win * NTOK + t) * QKVC + h * HDIM;
#pragma unroll
            for (int nt = 0; nt < 4; ++nt) {
                int d = nt * 8 + tig * 2;
                __half2 hv = __floats2half2_rn(oacc[mt][nt][hf * 2] * inv,
                                               oacc[mt][nt][hf * 2 + 1] * inv);
                *(__half2*)(qkv + ob + d) = hv;
            }
        }
    }
}

// ---------------- launch ----------------
extern "C" void kernel_launch(void* const* d_in, const int* in_sizes, int n_in,
                              void* d_out, int out_size) {
    const float* x      = (const float*)d_in[0];
    const float* g1     = (const float*)d_in[1];
    const float* be1    = (const float*)d_in[2];
    const float* w_qkv  = (const float*)d_in[3];
    const float* b_qkv  = (const float*)d_in[4];
    const float* pm_w1  = (const float*)d_in[5];
    const float* pm_b1  = (const float*)d_in[6];
    const float* pm_w2  = (const float*)d_in[7];
    const float* pm_b2  = (const float*)d_in[8];
    const float* w_proj = (const float*)d_in[9];
    const float* b_proj = (const float*)d_in[10];
    const float* g2     = (const float*)d_in[11];
    const float* be2    = (const float*)d_in[12];
    const float* w_fc1  = (const float*)d_in[13];
    const float* b_fc1  = (const float*)d_in[14];
    const float* w_fc2  = (const float*)d_in[15];
    const float* b_fc2  = (const float*)d_in[16];
    float* out = (float*)d_out;

    __half *p_xw, *p_qkv, *p_hidden, *p_wh;
    float *p_x1, *p_pbm;
    cudaGetSymbolAddress((void**)&p_xw, g_xw);
    cudaGetSymbolAddress((void**)&p_qkv, g_qkv);
    cudaGetSymbolAddress((void**)&p_x1, g_x1);
    cudaGetSymbolAddress((void**)&p_hidden, g_hidden);
    cudaGetSymbolAddress((void**)&p_wh, g_wh);
    cudaGetSymbolAddress((void**)&p_pbm, g_pbm);

    cudaFuncSetAttribute(tgemm<0>, cudaFuncAttributeMaxDynamicSharedMemorySize, TG_SMEM);
    cudaFuncSetAttribute(tgemm<1>, cudaFuncAttributeMaxDynamicSharedMemorySize, TG_SMEM);
    cudaFuncSetAttribute(tgemm<2>, cudaFuncAttributeMaxDynamicSharedMemorySize, TG_SMEM);
    cudaFuncSetAttribute(tgemm<3>, cudaFuncAttributeMaxDynamicSharedMemorySize, TG_SMEM);

    // 0. weight conversion + pos-bias fragment tables
    cvtw_kernel<<<WTOT / 4 / 256, 256>>>(w_qkv, w_proj, w_fc1, w_fc2);
    posbias_kernel<<<4 * NH, 256>>>(pm_w1, pm_b1, pm_w2, pm_b2);

    // 1. LN1 + shifted-window gather -> g_xw (fp16)
    ln_kernel<<<MROWS / 8, 256>>>(x, g1, be1, p_xw, 1);

    // 2. QKV GEMM -> g_qkv (fp16)
    tgemm<0><<<dim3(QKVC / 128, MROWS / 128), 128, TG_SMEM>>>(
        p_xw, CDIM, p_wh + WQ_OFF, CDIM, b_qkv, p_qkv, QKVC, CDIM, nullptr);

    // 3. tensor-core windowed attention (writes into q-region)
    attn_kernel<<<NWTOT * NH / 4, 128>>>(p_qkv, p_pbm);

    // 4. proj GEMM + window-reverse scatter + residual -> g_x1 (fp32)
    tgemm<1><<<dim3(CDIM / 128, MROWS / 128), 128, TG_SMEM>>>(
        p_qkv, QKVC, p_wh + WP_OFF, CDIM, b_proj, p_x1, CDIM, CDIM, x);

    // 5. LN2 -> g_xw (fp16)
    ln_kernel<<<MROWS / 8, 256>>>(p_x1, g2, be2, p_xw, 0);

    // 6. FC1 + GELU(erf) -> g_hidden (fp16)
    tgemm<2><<<dim3(HID / 128, MROWS / 128), 128, TG_SMEM>>>(
        p_xw, CDIM, p_wh + W1_OFF, CDIM, b_fc1, p_hidden, HID, CDIM, nullptr);

    // 7. FC2 + residual -> d_out (fp32)
    tgemm<3><<<dim3(CDIM / 128, MROWS / 128), 128, TG_SMEM>>>(
        p_hidden, HID, p_wh + W2_OFF, HID, b_fc2, out, CDIM, HID, p_x1);
}

// round 16
// speedup vs baseline: 1.0399x; 1.0172x over previous
#include <cuda_runtime.h>
#include <cuda_fp16.h>
#include <math.h>
#include <cstdint>

// ---------------- problem constants ----------------
#define BB    32
#define HH    56
#define WWI   56
#define LTOK  3136          // 56*56
#define CDIM  512
#define NH    16
#define HDIM  32
#define WSZ   8
#define NTOK  64            // 8*8
#define SHFT  4
#define NWH   7
#define NWIN  49            // 7*7
#define NWTOT 1568          // BB*NWIN
#define MROWS 100352        // BB*LTOK = NWTOT*NTOK
#define HID   2048
#define QKVC  1536

// weight offsets in g_wh (halves)
#define WQ_OFF  0
#define WP_OFF  786432            // 1536*512
#define W1_OFF  1048576           // + 512*512
#define W2_OFF  2097152           // + 2048*512
#define WTOT    3145728           // + 512*2048

// ---------------- static device scratch ----------------
__device__ __half g_xw[(size_t)MROWS * CDIM];      // LN outputs (fp16)
__device__ __half g_qkv[(size_t)MROWS * QKVC];     // qkv fp16; q-region reused as attn out
__device__ float  g_x1[(size_t)MROWS * CDIM];      // residual after attention (fp32)
__device__ __half g_hidden[(size_t)MROWS * HID];   // MLP hidden fp16
__device__ __half g_wh[WTOT];                      // fp16 weights
__device__ float  g_pbm[4 * NH * 4096];            // pos-bias + mask, fragment layout

// ---------------- helpers ----------------
__device__ __forceinline__ uint32_t smem_u32(const void* p) {
    uint32_t a;
    asm("{ .reg .u64 t; cvta.to.shared.u64 t, %1; cvt.u32.u64 %0, t; }" : "=r"(a) : "l"(p));
    return a;
}
#define CP_ASYNC16(dst, src) \
    asm volatile("cp.async.cg.shared.global [%0], [%1], 16;" :: "r"(dst), "l"(src))
#define CP_COMMIT() asm volatile("cp.async.commit_group;" ::: "memory")
#define CP_WAIT(n)  asm volatile("cp.async.wait_group %0;" :: "n"(n) : "memory")

#define LDSM4(r, addr) \
    asm volatile("ldmatrix.sync.aligned.m8n8.x4.shared.b16 {%0,%1,%2,%3}, [%4];" \
        : "=r"((r)[0]), "=r"((r)[1]), "=r"((r)[2]), "=r"((r)[3]) : "r"(addr))
#define LDSM4T(r, addr) \
    asm volatile("ldmatrix.sync.aligned.m8n8.x4.trans.shared.b16 {%0,%1,%2,%3}, [%4];" \
        : "=r"((r)[0]), "=r"((r)[1]), "=r"((r)[2]), "=r"((r)[3]) : "r"(addr))

__device__ __forceinline__ void mma_f16(float* d, const uint32_t* a, uint32_t b0, uint32_t b1) {
    asm volatile(
        "mma.sync.aligned.m16n8k16.row.col.f32.f16.f16.f32 "
        "{%0,%1,%2,%3}, {%4,%5,%6,%7}, {%8,%9}, {%0,%1,%2,%3};"
        : "+f"(d[0]), "+f"(d[1]), "+f"(d[2]), "+f"(d[3])
        : "r"(a[0]), "r"(a[1]), "r"(a[2]), "r"(a[3]), "r"(b0), "r"(b1));
}
// fp16-accumulator variant: D/C are 2x f16x2 regs
__device__ __forceinline__ void mma_f16h(uint32_t* d, const uint32_t* a, uint32_t b0, uint32_t b1) {
    asm volatile(
        "mma.sync.aligned.m16n8k16.row.col.f16.f16.f16.f16 "
        "{%0,%1}, {%2,%3,%4,%5}, {%6,%7}, {%0,%1};"
        : "+r"(d[0]), "+r"(d[1])
        : "r"(a[0]), "r"(a[1]), "r"(a[2]), "r"(a[3]), "r"(b0), "r"(b1));
}

// windowed row p -> flat row in original (B, H*W) layout
__device__ __forceinline__ size_t win_row_to_flat(int p) {
    int b   = p / LTOK;
    int rem = p - b * LTOK;
    int wl  = rem >> 6;
    int t   = rem & 63;
    int wh  = wl / NWH;
    int ww  = wl - wh * NWH;
    int r   = (wh * WSZ + (t >> 3) + SHFT) % HH;
    int c   = (ww * WSZ + (t & 7)  + SHFT) % WWI;
    return (size_t)b * LTOK + (size_t)r * WWI + c;
}

// ---------------- weight fp32 -> fp16 conversion ----------------
__global__ __launch_bounds__(256)
void cvtw_kernel(const float* __restrict__ wq, const float* __restrict__ wp,
                 const float* __restrict__ w1, const float* __restrict__ w2) {
    int i4 = (blockIdx.x * 256 + threadIdx.x) * 4;
    const float* src;
    int off;
    if      (i4 < WP_OFF) { src = wq; off = i4; }
    else if (i4 < W1_OFF) { src = wp; off = i4 - WP_OFF; }
    else if (i4 < W2_OFF) { src = w1; off = i4 - W1_OFF; }
    else                  { src = w2; off = i4 - W2_OFF; }
    float4 v = *(const float4*)(src + off);
    __half2 a = __floats2half2_rn(v.x, v.y);
    __half2 b = __floats2half2_rn(v.z, v.w);
    uint2 u;
    u.x = *(uint32_t*)&a;
    u.y = *(uint32_t*)&b;
    *(uint2*)&g_wh[i4] = u;
}

// ---------------- pos-bias + mask table, fragment layout ----------------
__global__ __launch_bounds__(256)
void posbias_kernel(const float* __restrict__ w1, const float* __restrict__ b1,
                    const float* __restrict__ w2, const float* __restrict__ b2) {
    int blk = blockIdx.x;            // cls*16 + h
    int cls = blk >> 4, h = blk & 15;
    int rh = cls >> 1, rw = cls & 1;
    for (int f = threadIdx.x; f < 1024; f += 256) {
        int lane = f & 31, f4 = (f >> 5) & 3, qc = f >> 7;
        int mt = qc >> 1, hf = qc & 1, g = lane >> 2, tig = lane & 3;
        int n = mt * 16 + g + 8 * hf;           // query token
        float out[4];
#pragma unroll
        for (int e = 0; e < 4; ++e) {
            int nt = f4 * 2 + (e >> 1), j = e & 1;
            int m = nt * 8 + tig * 2 + j;       // key token
            float dh = (float)((n >> 3) - (m >> 3));
            float dw = (float)((n & 7) - (m & 7));
            float fh = (dh > 0.f) ? log1pf(dh) : ((dh < 0.f) ? -log1pf(-dh) : 0.f);
            float fw = (dw > 0.f) ? log1pf(dw) : ((dw < 0.f) ? -log1pf(-dw) : 0.f);
            float acc = b2[h];
#pragma unroll
            for (int o = 0; o < 32; ++o) {
                float hv = fmaxf(w1[2 * o] * fh + w1[2 * o + 1] * fw + b1[o], 0.f);
                acc += w2[h * 32 + o] * hv;
            }
            int gin = rh ? (((n >> 3) < 4) ? 1 : 2) : 0;
            int gjn = rw ? (((n & 7) < 4) ? 1 : 2) : 0;
            int gim = rh ? (((m >> 3) < 4) ? 1 : 2) : 0;
            int gjm = rw ? (((m & 7) < 4) ? 1 : 2) : 0;
            if (gin != gim || gjn != gjm) acc -= 100.f;
            out[e] = acc;
        }
        *(float4*)&g_pbm[(size_t)blk * 4096 + f * 4] = make_float4(out[0], out[1], out[2], out[3]);
    }
}

// ---------------- LayerNorm: warp-per-row, fp32 in, fp16 out ----------------
__global__ __launch_bounds__(256)
void ln_kernel(const float* __restrict__ in, const float* __restrict__ gamma,
               const float* __restrict__ beta, __half* __restrict__ out, int gather) {
    int warp = threadIdx.x >> 5, lane = threadIdx.x & 31;
    int p = blockIdx.x * 8 + warp;
    size_t srow = gather ? win_row_to_flat(p) : (size_t)p;
    const float4* src = (const float4*)(in + srow * CDIM);
    float4 v[4];
#pragma unroll
    for (int i = 0; i < 4; ++i) v[i] = src[lane + 32 * i];
    float s = 0.f, q = 0.f;
#pragma unroll
    for (int i = 0; i < 4; ++i) {
        s += v[i].x + v[i].y + v[i].z + v[i].w;
        q += v[i].x * v[i].x + v[i].y * v[i].y + v[i].z * v[i].z + v[i].w * v[i].w;
    }
#pragma unroll
    for (int off = 16; off > 0; off >>= 1) {
        s += __shfl_xor_sync(0xFFFFFFFFu, s, off);
        q += __shfl_xor_sync(0xFFFFFFFFu, q, off);
    }
    float mean = s * (1.f / CDIM);
    float var  = q * (1.f / CDIM) - mean * mean;
    float rstd = rsqrtf(var + 1e-5f);
    uint2* dst = (uint2*)(out + (size_t)p * CDIM);
#pragma unroll
    for (int i = 0; i < 4; ++i) {
        int idx = lane + 32 * i;
        float4 gg = ((const float4*)gamma)[idx];
        float4 bb = ((const float4*)beta)[idx];
        float ox = (v[i].x - mean) * rstd * gg.x + bb.x;
        float oy = (v[i].y - mean) * rstd * gg.y + bb.y;
        float oz = (v[i].z - mean) * rstd * gg.z + bb.z;
        float ow = (v[i].w - mean) * rstd * gg.w + bb.w;
        __half2 h0 = __floats2half2_rn(ox, oy);
        __half2 h1 = __floats2half2_rn(oz, ow);
        uint2 u;
        u.x = *(uint32_t*)&h0;
        u.y = *(uint32_t*)&h1;
        dst[idx] = u;
    }
}

// ---------------- fp16 mma GEMM NT: 128x128 CTA, BK=64, swizzled smem ----------------
// 4 warps 2x2, warp tile 64x64, 3-stage cp.async, 2 CTAs/SM.
// MODE 0 (QKV) / MODE 2 (FC1): fp16 accumulators + fragment double-buffer.
// MODE 1 (proj) / MODE 3 (FC2): fp32 accumulators (residual spine), single-buffer.
#define BKH 64
#define STAGE_B 32768
#define B_OFF 16384
#define NSTAGE 3
#define TG_SMEM (NSTAGE * STAGE_B)

template<int MODE>
__global__ __launch_bounds__(128, 2)
void tgemm(const __half* __restrict__ A, int lda,
           const __half* __restrict__ B, int ldb,
           const float* __restrict__ bias,
           void* __restrict__ Cv, int ldc, int K,
           const float* __restrict__ res) {
    constexpr bool HACC = (MODE == 0 || MODE == 2);
    extern __shared__ __half smh[];
    uint32_t sb = smem_u32(smh);

    int tid = threadIdx.x;
    int wid = tid >> 5, lane = tid & 31;
    int g   = lane >> 2;
    int tig = lane & 3;
    int hh  = lane >> 4;
    int warp_row = wid >> 1;
    int warp_col = wid & 1;

    const __half* Ag = A + (size_t)(blockIdx.y * 128) * lda;
    const __half* Bg = B + (size_t)(blockIdx.x * 128) * ldb;

    int cr[8], cc_[8], csw[8];
#pragma unroll
    for (int i = 0; i < 8; ++i) {
        int task = i * 128 + tid;
        cr[i]  = task >> 3;
        cc_[i] = task & 7;
        csw[i] = (cc_[i] ^ (cr[i] & 7)) << 4;
    }

    uint32_t abase[4], bbase[4];
    int a7[4], b7[4];
#pragma unroll
    for (int mt = 0; mt < 4; ++mt) {
        int row = warp_row * 64 + mt * 16 + (lane & 15);
        abase[mt] = (uint32_t)(row * 128);
        a7[mt] = row & 7;
    }
#pragma unroll
    for (int p = 0; p < 4; ++p) {
        int row = warp_col * 64 + p * 16 + (lane & 15);
        bbase[p] = (uint32_t)(B_OFF + row * 128);
        b7[p] = row & 7;
    }

    float    accf[4][8][4];
    uint32_t acch[4][8][2];
    if (HACC) {
#pragma unroll
        for (int mt = 0; mt < 4; ++mt)
#pragma unroll
            for (int nt = 0; nt < 8; ++nt) { acch[mt][nt][0] = 0u; acch[mt][nt][1] = 0u; }
    } else {
#pragma unroll
        for (int mt = 0; mt < 4; ++mt)
#pragma unroll
            for (int nt = 0; nt < 8; ++nt)
#pragma unroll
                for (int j = 0; j < 4; ++j) accf[mt][nt][j] = 0.f;
    }

    int ntiles = K / BKH;

#pragma unroll
    for (int s = 0; s < 2; ++s) {
        int k0 = s * BKH;
        uint32_t st = sb + s * STAGE_B;
#pragma unroll
        for (int i = 0; i < 8; ++i) {
            CP_ASYNC16(st + cr[i] * 128 + csw[i],
                       Ag + (size_t)cr[i] * lda + k0 + cc_[i] * 8);
            CP_ASYNC16(st + B_OFF + cr[i] * 128 + csw[i],
                       Bg + (size_t)cr[i] * ldb + k0 + cc_[i] * 8);
        }
        CP_COMMIT();
    }

    int stage = 0;
    for (int t = 0; t < ntiles; ++t) {
        CP_WAIT(1);
        __syncthreads();
        if (t + 2 < ntiles) {
            int k0 = (t + 2) * BKH;
            int s2 = stage + 2; if (s2 >= NSTAGE) s2 -= NSTAGE;
            uint32_t st = sb + s2 * STAGE_B;
#pragma unroll
            for (int i = 0; i < 8; ++i) {
                CP_ASYNC16(st + cr[i] * 128 + csw[i],
                           Ag + (size_t)cr[i] * lda + k0 + cc_[i] * 8);
                CP_ASYNC16(st + B_OFF + cr[i] * 128 + csw[i],
                           Bg + (size_t)cr[i] * ldb + k0 + cc_[i] * 8);
            }
        }
        CP_COMMIT();

        uint32_t sbase = sb + stage * STAGE_B;
        if (HACC) {
            // fragment double-buffered mainloop (fits in regs with f16 acc)
            uint32_t af[2][4][4], bf[2][4][4];
            {
                int cc2 = hh;
#pragma unroll
                for (int mt = 0; mt < 4; ++mt)
                    LDSM4(af[0][mt], sbase + abase[mt] + (uint32_t)((cc2 ^ a7[mt]) << 4));
#pragma unroll
                for (int p = 0; p < 4; ++p)
                    LDSM4(bf[0][p], sbase + bbase[p] + (uint32_t)((cc2 ^ b7[p]) << 4));
            }
#pragma unroll
            for (int ks = 0; ks < 4; ++ks) {
                int cur = ks & 1;
                if (ks < 3) {
                    int nb = cur ^ 1;
                    int cc2 = (ks + 1) * 2 + hh;
#pragma unroll
                    for (int mt = 0; mt < 4; ++mt)
                        LDSM4(af[nb][mt], sbase + abase[mt] + (uint32_t)((cc2 ^ a7[mt]) << 4));
#pragma unroll
                    for (int p = 0; p < 4; ++p)
                        LDSM4(bf[nb][p], sbase + bbase[p] + (uint32_t)((cc2 ^ b7[p]) << 4));
                }
#pragma unroll
                for (int mt = 0; mt < 4; ++mt)
#pragma unroll
                    for (int p = 0; p < 4; ++p) {
                        mma_f16h(acch[mt][2 * p + 0], af[cur][mt], bf[cur][p][0], bf[cur][p][2]);
                        mma_f16h(acch[mt][2 * p + 1], af[cur][mt], bf[cur][p][1], bf[cur][p][3]);
                    }
            }
        } else {
#pragma unroll
            for (int ks = 0; ks < 4; ++ks) {
                int cc2 = ks * 2 + hh;
                uint32_t af[4][4], bf[4][4];
#pragma unroll
                for (int mt = 0; mt < 4; ++mt)
                    LDSM4(af[mt], sbase + abase[mt] + (uint32_t)((cc2 ^ a7[mt]) << 4));
#pragma unroll
                for (int p = 0; p < 4; ++p)
                    LDSM4(bf[p], sbase + bbase[p] + (uint32_t)((cc2 ^ b7[p]) << 4));
#pragma unroll
                for (int mt = 0; mt < 4; ++mt)
#pragma unroll
                    for (int p = 0; p < 4; ++p) {
                        mma_f16(accf[mt][2 * p + 0], af[mt], bf[p][0], bf[p][2]);
                        mma_f16(accf[mt][2 * p + 1], af[mt], bf[p][1], bf[p][3]);
                    }
            }
        }
        if (++stage >= NSTAGE) stage -= NSTAGE;
    }

    // ---------------- epilogue ----------------
    int gr_base = blockIdx.y * 128 + warp_row * 64;
    int gc_base = blockIdx.x * 128 + warp_col * 64;

    __half* Ch = (__half*)Cv;
    float*  Cf = (float*)Cv;

#pragma unroll
    for (int mt = 0; mt < 4; ++mt) {
#pragma unroll
        for (int hf = 0; hf < 2; ++hf) {
            int gr = gr_base + mt * 16 + g + hf * 8;
            size_t crow = (MODE == 1) ? win_row_to_flat(gr) * (size_t)ldc : (size_t)gr * ldc;
#pragma unroll
            for (int nt = 0; nt < 8; ++nt) {
                int col = gc_base + nt * 8 + tig * 2;
                float2 bs = *(const float2*)&bias[col];
                float v0, v1;
                if (HACC) {
                    __half2 hv = *(__half2*)&acch[mt][nt][hf];
                    float2 fv = __half22float2(hv);
                    v0 = fv.x; v1 = fv.y;
                } else {
                    v0 = accf[mt][nt][hf * 2 + 0];
                    v1 = accf[mt][nt][hf * 2 + 1];
                }
                v0 += bs.x; v1 += bs.y;
                if (MODE == 2) {
                    v0 = 0.5f * v0 * (1.0f + erff(v0 * 0.70710678118654752f));
                    v1 = 0.5f * v1 * (1.0f + erff(v1 * 0.70710678118654752f));
                }
                if (MODE == 1 || MODE == 3) {
                    float2 rr = *(const float2*)&res[crow + col];
                    v0 += rr.x; v1 += rr.y;
                    *(float2*)&Cf[crow + col] = make_float2(v0, v1);
                } else {
                    __half2 hv = __floats2half2_rn(v0, v1);
                    *(__half2*)&Ch[crow + col] = hv;
                }
            }
        }
    }
}

// ---------------- tensor-core windowed attention: 1 warp per (window, head) ----------------
__global__ __launch_bounds__(128)
void attn_kernel(__half* __restrict__ qkv, const float* __restrict__ pbm) {
    __shared__ __align__(16) uint8_t sm[49152];

    int tid = threadIdx.x, wid = tid >> 5, lane = tid & 31;
    int gid = blockIdx.x * 4 + wid;
    int win = gid >> 4, h = gid & 15;
    int wl  = win % NWIN;
    int wh  = wl / NWH;
    int ww  = wl - wh * NWH;
    int cls = ((wh == 6) ? 2 : 0) + ((ww == 6) ? 1 : 0);

    uint8_t* wsm = sm + wid * 12288;
    uint32_t sbase = smem_u32(wsm);
    const float scale = 0.17677669529663687f;

    for (int i = lane; i < 256; i += 32) {
        int row = i >> 2, c = i & 3;
        size_t gbase = (size_t)(win * NTOK + row) * QKVC + h * HDIM + c * 8;
        uint4 qu = *(const uint4*)(qkv + gbase);
        uint4 ku = *(const uint4*)(qkv + gbase + CDIM);
        uint4 vu = *(const uint4*)(qkv + gbase + 2 * CDIM);
        int sw = row * 64 + ((c ^ ((row >> 1) & 3)) << 4);
        *(uint4*)(wsm + sw)         = qu;
        *(uint4*)(wsm + 4096 + sw)  = ku;
        *(uint4*)(wsm + 8192 + sw)  = vu;
    }
    __syncwarp();

    float acc[4][8][4];
#pragma unroll
    for (int mt = 0; mt < 4; ++mt)
#pragma unroll
        for (int nt = 0; nt < 8; ++nt)
#pragma unroll
            for (int j = 0; j < 4; ++j) acc[mt][nt][j] = 0.f;

#pragma unroll
    for (int ks = 0; ks < 2; ++ks) {
        uint32_t af[4][4], bf[4][4];
#pragma unroll
        for (int mt = 0; mt < 4; ++mt) {
            int row = mt * 16 + (lane & 15);
            int ch = (ks * 2 + (lane >> 4)) ^ ((row >> 1) & 3);
            LDSM4(af[mt], sbase + row * 64 + (ch << 4));
        }
#pragma unroll
        for (int p = 0; p < 4; ++p) {
            int row = p * 16 + (lane & 15);
            int ch = (ks * 2 + (lane >> 4)) ^ ((row >> 1) & 3);
            LDSM4(bf[p], sbase + 4096 + row * 64 + (ch << 4));
        }
#pragma unroll
        for (int mt = 0; mt < 4; ++mt)
#pragma unroll
            for (int p = 0; p < 4; ++p) {
                mma_f16(acc[mt][2 * p + 0], af[mt], bf[p][0], bf[p][2]);
                mma_f16(acc[mt][2 * p + 1], af[mt], bf[p][1], bf[p][3]);
            }
    }

    const float* pbb = pbm + (size_t)(cls * NH + h) * 4096;
    float inv_[4][2];
#pragma unroll
    for (int mt = 0; mt < 4; ++mt) {
#pragma unroll
        for (int hf = 0; hf < 2; ++hf) {
            int qc = mt * 2 + hf;
            float s[16];
            float mx = -1e30f;
#pragma unroll
            for (int f4 = 0; f4 < 4; ++f4) {
                float4 pv = *(const float4*)&pbb[((qc * 4 + f4) * 32 + lane) * 4];
                float pe[4] = {pv.x, pv.y, pv.z, pv.w};
#pragma unroll
                for (int e = 0; e < 4; ++e) {
                    int nt = f4 * 2 + (e >> 1), j = e & 1;
                    float v = acc[mt][nt][hf * 2 + j] * scale + pe[e];
                    s[f4 * 4 + e] = v;
                    mx = fmaxf(mx, v);
                }
            }
            mx = fmaxf(mx, __shfl_xor_sync(0xFFFFFFFFu, mx, 1));
            mx = fmaxf(mx, __shfl_xor_sync(0xFFFFFFFFu, mx, 2));
            float sum = 0.f;
#pragma unroll
            for (int i = 0; i < 16; ++i) {
                float e_ = __expf(s[i] - mx);
                s[i] = e_;
                sum += e_;
            }
            sum += __shfl_xor_sync(0xFFFFFFFFu, sum, 1);
            sum += __shfl_xor_sync(0xFFFFFFFFu, sum, 2);
            inv_[mt][hf] = 1.f / sum;
#pragma unroll
            for (int f4 = 0; f4 < 4; ++f4)
#pragma unroll
                for (int e = 0; e < 4; ++e)
                    acc[mt][f4 * 2 + (e >> 1)][hf * 2 + (e & 1)] = s[f4 * 4 + e];
        }
    }

    uint32_t ph[4][4][4];
#pragma unroll
    for (int mt = 0; mt < 4; ++mt)
#pragma unroll
        for (int ks = 0; ks < 4; ++ks) {
            __half2 h0 = __floats2half2_rn(acc[mt][2 * ks][0], acc[mt][2 * ks][1]);
            __half2 h1 = __floats2half2_rn(acc[mt][2 * ks][2], acc[mt][2 * ks][3]);
            __half2 h2 = __floats2half2_rn(acc[mt][2 * ks + 1][0], acc[mt][2 * ks + 1][1]);
            __half2 h3 = __floats2half2_rn(acc[mt][2 * ks + 1][2], acc[mt][2 * ks + 1][3]);
            ph[mt][ks][0] = *(uint32_t*)&h0;
            ph[mt][ks][1] = *(uint32_t*)&h1;
            ph[mt][ks][2] = *(uint32_t*)&h2;
            ph[mt][ks][3] = *(uint32_t*)&h3;
        }

    float oacc[4][4][4];
#pragma unroll
    for (int mt = 0; mt < 4; ++mt)
#pragma unroll
        for (int nt = 0; nt < 4; ++nt)
#pragma unroll
            for (int j = 0; j < 4; ++j) oacc[mt][nt][j] = 0.f;

#pragma unroll
    for (int ks = 0; ks < 4; ++ks) {
        int token = ks * 16 + (lane & 15);
        int chA = (0 + (lane >> 4)) ^ ((token >> 1) & 3);
        int chB = (2 + (lane >> 4)) ^ ((token >> 1) & 3);
        uint32_t vfa[4], vfb[4];
        LDSM4T(vfa, sbase + 8192 + token * 64 + (chA << 4));
        LDSM4T(vfb, sbase + 8192 + token * 64 + (chB << 4));
#pragma unroll
        for (int mt = 0; mt < 4; ++mt) {
            mma_f16(oacc[mt][0], ph[mt][ks], vfa[0], vfa[1]);
            mma_f16(oacc[mt][1], ph[mt][ks], vfa[2], vfa[3]);
            mma_f16(oacc[mt][2], ph[mt][ks], vfb[0], vfb[1]);
            mma_f16(oacc[mt][3], ph[mt][ks], vfb[2], vfb[3]);
        }
    }

    int g = lane >> 2, tig = lane & 3;
#pragma unroll
    for (int mt = 0; mt < 4; ++mt) {
#pragma unroll
        for (int hf = 0; hf < 2; ++hf) {
            int t = mt * 16 + g + 8 * hf;
            float inv = inv_[mt][hf];
            size_t ob = (size_t)(win * NTOK + t) * QKVC + h * HDIM;
#pragma unroll
            for (int nt = 0; nt < 4; ++nt) {
                int d = nt * 8 + tig * 2;
                __half2 hv = __floats2half2_rn(oacc[mt][nt][hf * 2] * inv,
                                               oacc[mt][nt][hf * 2 + 1] * inv);
                *(__half2*)(qkv + ob + d) = hv;
            }
        }
    }
}

// ---------------- launch ----------------
extern "C" void kernel_launch(void* const* d_in, const int* in_sizes, int n_in,
                              void* d_out, int out_size) {
    const float* x      = (const float*)d_in[0];
    const float* g1     = (const float*)d_in[1];
    const float* be1    = (const float*)d_in[2];
    const float* w_qkv  = (const float*)d_in[3];
    const float* b_qkv  = (const float*)d_in[4];
    const float* pm_w1  = (const float*)d_in[5];
    const float* pm_b1  = (const float*)d_in[6];
    const float* pm_w2  = (const float*)d_in[7];
    const float* pm_b2  = (const float*)d_in[8];
    const float* w_proj = (const float*)d_in[9];
    const float* b_proj = (const float*)d_in[10];
    const float* g2     = (const float*)d_in[11];
    const float* be2    = (const float*)d_in[12];
    const float* w_fc1  = (const float*)d_in[13];
    const float* b_fc1  = (const float*)d_in[14];
    const float* w_fc2  = (const float*)d_in[15];
    const float* b_fc2  = (const float*)d_in[16];
    float* out = (float*)d_out;

    __half *p_xw, *p_qkv, *p_hidden, *p_wh;
    float *p_x1, *p_pbm;
    cudaGetSymbolAddress((void**)&p_xw, g_xw);
    cudaGetSymbolAddress((void**)&p_qkv, g_qkv);
    cudaGetSymbolAddress((void**)&p_x1, g_x1);
    cudaGetSymbolAddress((void**)&p_hidden, g_hidden);
    cudaGetSymbolAddress((void**)&p_wh, g_wh);
    cudaGetSymbolAddress((void**)&p_pbm, g_pbm);

    cudaFuncSetAttribute(tgemm<0>, cudaFuncAttributeMaxDynamicSharedMemorySize, TG_SMEM);
    cudaFuncSetAttribute(tgemm<1>, cudaFuncAttributeMaxDynamicSharedMemorySize, TG_SMEM);
    cudaFuncSetAttribute(tgemm<2>, cudaFuncAttributeMaxDynamicSharedMemorySize, TG_SMEM);
    cudaFuncSetAttribute(tgemm<3>, cudaFuncAttributeMaxDynamicSharedMemorySize, TG_SMEM);

    // 0. weight conversion + pos-bias fragment tables
    cvtw_kernel<<<WTOT / 4 / 256, 256>>>(w_qkv, w_proj, w_fc1, w_fc2);
    posbias_kernel<<<4 * NH, 256>>>(pm_w1, pm_b1, pm_w2, pm_b2);

    // 1. LN1 + shifted-window gather -> g_xw (fp16)
    ln_kernel<<<MROWS / 8, 256>>>(x, g1, be1, p_xw, 1);

    // 2. QKV GEMM (f16 acc + frag double-buffer) -> g_qkv (fp16)
    tgemm<0><<<dim3(QKVC / 128, MROWS / 128), 128, TG_SMEM>>>(
        p_xw, CDIM, p_wh + WQ_OFF, CDIM, b_qkv, p_qkv, QKVC, CDIM, nullptr);

    // 3. tensor-core windowed attention (writes into q-region)
    attn_kernel<<<NWTOT * NH / 4, 128>>>(p_qkv, p_pbm);

    // 4. proj GEMM (fp32 acc) + window-reverse scatter + residual -> g_x1 (fp32)
    tgemm<1><<<dim3(CDIM / 128, MROWS / 128), 128, TG_SMEM>>>(
        p_qkv, QKVC, p_wh + WP_OFF, CDIM, b_proj, p_x1, CDIM, CDIM, x);

    // 5. LN2 -> g_xw (fp16)
    ln_kernel<<<MROWS / 8, 256>>>(p_x1, g2, be2, p_xw, 0);

    // 6. FC1 (f16 acc + frag double-buffer) + GELU(erf) -> g_hidden (fp16)
    tgemm<2><<<dim3(HID / 128, MROWS / 128), 128, TG_SMEM>>>(
        p_xw, CDIM, p_wh + W1_OFF, CDIM, b_fc1, p_hidden, HID, CDIM, nullptr);

    // 7. FC2 (fp32 acc) + residual -> d_out (fp32)
    tgemm<3><<<dim3(CDIM / 128, MROWS / 128), 128, TG_SMEM>>>(
        p_hidden, HID, p_wh + W2_OFF, HID, b_fc2, out, CDIM, HID, p_x1);
}